// round 13
// baseline (speedup 1.0000x reference)
#include <cuda_runtime.h>
#include <cstdint>

#define N_USERS 50000
#define N_ITEMS 75000
#define N_NODES 125000
#define NNZ     1250000
#define EMB     64
#define N_LAYERS 3
#define BATCH   4096
#define SCAN_BLOCKS 489        // ceil(125000/256)

// Scratch (device globals — allocation-free per harness rules)
__device__ __align__(128) float g_fL0 [N_NODES * EMB];                 // 32 MB
__device__ __align__(128) float g_fL1 [N_NODES * EMB];                 // 32 MB
__device__ __align__(128) float g_fL2 [N_NODES * EMB];                 // 32 MB
__device__ __align__(128) float g_agg [N_NODES * EMB];                 // 32 MB
__device__ __align__(128) float g_inv [N_LAYERS * N_NODES];            // per-node 1/||o||
// CSR scratch.  INVARIANT: g_cnt and g_desc are all-zero at kernel_launch
// entry (zero-initialized at load; re-zeroed by gather_kernel every run).
__device__ __align__(128) int      g_cnt   [N_NODES];
__device__ __align__(128) int2     g_rowse [N_NODES];    // (start, end) per row
__device__ __align__(128) int      g_cursor[N_NODES];
__device__ __align__(128) unsigned g_desc  [512];        // lookback descriptors
__device__ __align__(128) int2     g_edge  [NNZ];        // (col, val_bits) packed

#define FLAG_AGG 0x40000000u
#define FLAG_PRE 0x80000000u
#define VAL_MASK 0x3FFFFFFFu

__device__ __forceinline__ float lrelu(float x) {
    return x > 0.0f ? x : 0.2f * x;
}

// Packed fp32x2 FMA (sm_103a FFMA2)
#define FMA2(acc, a, b) \
    asm("fma.rn.f32x2 %0, %1, %2, %0;" : "+l"(acc) : "l"(a), "l"(b))
#define PACK2(d, s) \
    asm("mov.b64 %0, {%1, %1};" : "=l"(d) : "f"(s))

__device__ __forceinline__ float lo2(unsigned long long v) {
    return __uint_as_float((unsigned)v);
}
__device__ __forceinline__ float hi2(unsigned long long v) {
    return __uint_as_float((unsigned)(v >> 32));
}

// Device-side buffer selection (NEVER pass __device__ symbols from host!)
__device__ __forceinline__ const float* feat_in_for(const float* emb, int layer) {
    return (layer == 0) ? emb : (layer == 1 ? g_fL0 : g_fL1);
}
__device__ __forceinline__ float* feat_out_for(int layer) {
    return (layer == 0) ? g_fL0 : (layer == 1 ? g_fL1 : g_fL2);
}
__device__ __forceinline__ const float* feat_layer(int l) {
    return (l == 0) ? g_fL0 : (l == 1 ? g_fL1 : g_fL2);
}

// ---------------------------------------------------------------------------
// histogram rows (g_cnt zero on entry, see invariant)
__global__ __launch_bounds__(256) void hist_kernel(const int* __restrict__ row) {
    int e = blockIdx.x * 256 + threadIdx.x;
    if (e < NNZ) atomicAdd(&g_cnt[row[e]], 1);
}

// ---------------------------------------------------------------------------
// Single-pass exclusive scan of g_cnt with decoupled lookback.
// Emits packed (start, end) per row + cursor.
__global__ __launch_bounds__(256) void scan_lookback_kernel() {
    __shared__ int wt[8];
    __shared__ int s_run;
    const int tid  = threadIdx.x;
    const int lane = tid & 31;
    const int w    = tid >> 5;
    const int b    = blockIdx.x;
    const int i    = b * 256 + tid;

    int x = (i < N_NODES) ? g_cnt[i] : 0;
    int v = x;
    #pragma unroll
    for (int off = 1; off < 32; off <<= 1) {
        int n = __shfl_up_sync(0xffffffffu, v, off);
        if (lane >= off) v += n;
    }
    if (lane == 31) wt[w] = v;
    __syncthreads();
    if (w == 0 && lane < 8) {
        int s = wt[lane];
        #pragma unroll
        for (int off = 1; off < 8; off <<= 1) {
            int n = __shfl_up_sync(0x000000ffu, s, off);
            if (lane >= off) s += n;
        }
        wt[lane] = s;
    }
    __syncthreads();
    const int add  = (w > 0) ? wt[w - 1] : 0;
    const int excl = v - x + add;
    __syncthreads();
    const int agg  = wt[7];

    if (tid == 0) {
        if (b == 0) {
            atomicExch(&g_desc[0], FLAG_PRE | (unsigned)agg);
            s_run = 0;
        } else {
            atomicExch(&g_desc[b], FLAG_AGG | (unsigned)agg);
            int run = 0;
            int p = b - 1;
            while (true) {
                unsigned s;
                do { s = atomicAdd(&g_desc[p], 0u); } while (s == 0u);
                run += (int)(s & VAL_MASK);
                if (s & FLAG_PRE) break;
                --p;
            }
            atomicExch(&g_desc[b], FLAG_PRE | (unsigned)(run + agg));
            s_run = run;
        }
    }
    __syncthreads();
    const int start = s_run + excl;
    if (i < N_NODES) {
        g_rowse [i] = make_int2(start, start + x);
        g_cursor[i] = start;
    }
}

// scatter edges into row-sorted order, packed (col, val) int2
__global__ __launch_bounds__(256) void scatter_kernel(const int*   __restrict__ row,
                                                      const int*   __restrict__ col,
                                                      const float* __restrict__ vals) {
    int e = blockIdx.x * 256 + threadIdx.x;
    if (e >= NNZ) return;
    int pos = atomicAdd(&g_cursor[row[e]], 1);
    g_edge[pos] = make_int2(col[e], __float_as_int(vals[e]));
}

// ---------------------------------------------------------------------------
// Gather-SpMM over CSR: packed int2 edges + packed (start,end) rowptr.
__global__ __launch_bounds__(256) void spmm_csr_kernel(const float* __restrict__ emb,
                                                       int layer) {
    int t   = blockIdx.x * 256 + threadIdx.x;
    int r   = t >> 4;
    int seg = t & 15;
    if (r >= N_NODES) return;
    const float4* feat4 = (const float4*)feat_in_for(emb, layer);
    int2 se = __ldg(g_rowse + r);
    int j  = se.x;
    int s1 = se.y;
    float4 acc = make_float4(0.f, 0.f, 0.f, 0.f);
    for (; j + 3 < s1; j += 4) {
        int2 e0 = __ldg(g_edge + j);
        int2 e1 = __ldg(g_edge + j + 1);
        int2 e2 = __ldg(g_edge + j + 2);
        int2 e3 = __ldg(g_edge + j + 3);
        float4 f0 = __ldg(feat4 + e0.x * 16 + seg);
        float4 f1 = __ldg(feat4 + e1.x * 16 + seg);
        float4 f2 = __ldg(feat4 + e2.x * 16 + seg);
        float4 f3 = __ldg(feat4 + e3.x * 16 + seg);
        float v0 = __int_as_float(e0.y);
        float v1 = __int_as_float(e1.y);
        float v2 = __int_as_float(e2.y);
        float v3 = __int_as_float(e3.y);
        acc.x += v0 * f0.x + v1 * f1.x + v2 * f2.x + v3 * f3.x;
        acc.y += v0 * f0.y + v1 * f1.y + v2 * f2.y + v3 * f3.y;
        acc.z += v0 * f0.z + v1 * f1.z + v2 * f2.z + v3 * f3.z;
        acc.w += v0 * f0.w + v1 * f1.w + v2 * f2.w + v3 * f3.w;
    }
    for (; j < s1; ++j) {
        int2 e0 = __ldg(g_edge + j);
        float4 f0 = __ldg(feat4 + e0.x * 16 + seg);
        float v0 = __int_as_float(e0.y);
        acc.x += v0 * f0.x;
        acc.y += v0 * f0.y;
        acc.z += v0 * f0.z;
        acc.w += v0 * f0.w;
    }
    ((float4*)g_agg)[r * 16 + seg] = acc;
}

// ---------------------------------------------------------------------------
// Dense per-node update.  THIS ROUND'S EXPERIMENT: k-major A staging
// (conflict-free STS, LDS.128 node-quads in the main loop — the R5 layout
// WITHOUT the persistence that caused R5's regression).  Grid = 977.
#define M_TILE    128
#define DN_STRIDE 132                                 // 128 nodes + 4 pad
#define W_STRIDE  68
#define SA_FLOATS (64 * DN_STRIDE)                    // 8448
#define SW_FLOATS (64 * W_STRIDE)                     // 4352
#define DENSE_SMEM ((2 * SA_FLOATS + 2 * SW_FLOATS) * 4)   // 102400 B

__global__ __launch_bounds__(256, 2) void dense_kernel(const float* __restrict__ emb,
                                                       const float* __restrict__ W1,
                                                       const float* __restrict__ b1,
                                                       const float* __restrict__ W2,
                                                       const float* __restrict__ b2,
                                                       int layer) {
    extern __shared__ float smem[];
    float* sA  = smem;                       // [64 k][128 nodes + pad]
    float* sAF = sA  + SA_FLOATS;
    float* sW1 = sAF + SA_FLOATS;            // [64 k][64 j] padded
    float* sW2 = sW1 + SW_FLOATS;

    const float* feat_in  = feat_in_for(emb, layer);
    float*       feat_out = feat_out_for(layer);

    const int t    = threadIdx.x;
    const int tx   = t & 15;
    const int ty   = t >> 4;
    const int j0   = tx * 4;
    const int m0   = ty * 8;
    const int base = blockIdx.x * M_TILE;

    const float* W1l = W1 + layer * 4096;
    const float* W2l = W2 + layer * 4096;
    #pragma unroll
    for (int i = t; i < 4096; i += 256) {
        int j = i >> 6, k = i & 63;
        sW1[k * W_STRIDE + j] = W1l[i];
        sW2[k * W_STRIDE + j] = W2l[i];
    }

    // Stage A (k-major): lanes span nodes -> conflict-free STS
    #pragma unroll
    for (int idx = t; idx < M_TILE * 16; idx += 256) {
        int mm = idx & 127;
        int sg = idx >> 7;                 // 0..15
        int node = base + mm;
        float4 a4 = make_float4(0.f, 0.f, 0.f, 0.f);
        float4 f4 = make_float4(0.f, 0.f, 0.f, 0.f);
        if (node < N_NODES) {
            a4 = ((const float4*)g_agg  )[node * 16 + sg];
            f4 = ((const float4*)feat_in)[node * 16 + sg];
        }
        #pragma unroll
        for (int i = 0; i < 4; ++i) {
            float av = (&a4.x)[i];
            float fv = (&f4.x)[i];
            int off = (sg * 4 + i) * DN_STRIDE + mm;
            sA [off] = av;
            sAF[off] = av * fv;
        }
    }
    __syncthreads();

    unsigned long long acc1[16], acc2[16];   // [j*4 + pair]
    #pragma unroll
    for (int i = 0; i < 16; ++i) { acc1[i] = 0ull; acc2[i] = 0ull; }

    #pragma unroll 4
    for (int k = 0; k < 64; ++k) {
        const float* rowA  = sA  + k * DN_STRIDE + m0;
        const float* rowAF = sAF + k * DN_STRIDE + m0;
        ulonglong2 A01  = *(const ulonglong2*)(rowA);
        ulonglong2 A23  = *(const ulonglong2*)(rowA + 4);
        ulonglong2 AF01 = *(const ulonglong2*)(rowAF);
        ulonglong2 AF23 = *(const ulonglong2*)(rowAF + 4);
        float4 w1 = *(const float4*)(sW1 + k * W_STRIDE + j0);
        float4 w2 = *(const float4*)(sW2 + k * W_STRIDE + j0);
        #pragma unroll
        for (int j = 0; j < 4; ++j) {
            unsigned long long wd1, wd2;
            PACK2(wd1, (&w1.x)[j]);
            PACK2(wd2, (&w2.x)[j]);
            FMA2(acc1[j * 4 + 0], A01.x,  wd1);
            FMA2(acc1[j * 4 + 1], A01.y,  wd1);
            FMA2(acc1[j * 4 + 2], A23.x,  wd1);
            FMA2(acc1[j * 4 + 3], A23.y,  wd1);
            FMA2(acc2[j * 4 + 0], AF01.x, wd2);
            FMA2(acc2[j * 4 + 1], AF01.y, wd2);
            FMA2(acc2[j * 4 + 2], AF23.x, wd2);
            FMA2(acc2[j * 4 + 3], AF23.y, wd2);
        }
    }

    float bb1[4], bb2[4];
    #pragma unroll
    for (int j = 0; j < 4; ++j) {
        bb1[j] = __ldg(b1 + layer * 64 + j0 + j);
        bb2[j] = __ldg(b2 + layer * 64 + j0 + j);
    }
    float* invL = g_inv + layer * N_NODES;

    #pragma unroll
    for (int mp = 0; mp < 4; ++mp) {
        #pragma unroll
        for (int h = 0; h < 2; ++h) {
            float o[4];
            #pragma unroll
            for (int j = 0; j < 4; ++j) {
                unsigned long long v1 = acc1[j * 4 + mp];
                unsigned long long v2 = acc2[j * 4 + mp];
                float a1 = (h ? hi2(v1) : lo2(v1)) + bb1[j];
                float a2 = (h ? hi2(v2) : lo2(v2)) + bb2[j];
                o[j] = lrelu(a1) + lrelu(a2);
            }
            float ss = o[0]*o[0] + o[1]*o[1] + o[2]*o[2] + o[3]*o[3];
            #pragma unroll
            for (int off = 8; off; off >>= 1)
                ss += __shfl_xor_sync(0xffffffffu, ss, off);
            float inv = __fdividef(1.0f, fmaxf(sqrtf(ss), 1e-12f));

            int node = base + m0 + mp * 2 + h;
            if (node < N_NODES) {
                float4 ov = make_float4(o[0], o[1], o[2], o[3]);
                ((float4*)feat_out)[node * 16 + tx] = ov;
                if (tx == 0) invL[node] = inv;
            }
        }
    }
}

// ---------------------------------------------------------------------------
// Final gather: out row = concat(emb, n0, n1, n2), nL = feat_L * inv_L.
// Also re-zeroes g_cnt and g_desc to maintain the entry invariant.
__global__ __launch_bounds__(256) void gather_kernel(const int* __restrict__ user,
                                                     const int* __restrict__ pos,
                                                     const int* __restrict__ neg,
                                                     const float* __restrict__ emb,
                                                     float* __restrict__ out) {
    int o4 = blockIdx.x * 256 + threadIdx.x;
    if (o4 < N_NODES) g_cnt[o4] = 0;               // restore invariant
    if (o4 < 512)     g_desc[o4] = 0u;             // restore invariant
    if (o4 >= 3 * BATCH * 64) return;
    int c4 = o4 & 63;
    int rr = o4 >> 6;
    int tsel = rr / BATCH;
    int r    = rr - tsel * BATCH;
    int node = (tsel == 0) ? user[r]
             : (tsel == 1) ? (N_USERS + pos[r])
                           : (N_USERS + neg[r]);
    int part = c4 >> 4;
    int cc   = c4 & 15;
    float4 v;
    if (part == 0) {
        v = ((const float4*)emb)[node * 16 + cc];
    } else {
        int l = part - 1;
        v = ((const float4*)feat_layer(l))[node * 16 + cc];
        float inv = g_inv[l * N_NODES + node];
        v.x *= inv; v.y *= inv; v.z *= inv; v.w *= inv;
    }
    ((float4*)out)[o4] = v;
}

// ---------------------------------------------------------------------------
extern "C" void kernel_launch(void* const* d_in, const int* in_sizes, int n_in,
                              void* d_out, int out_size) {
    const int*   user = (const int*)  d_in[0];
    const int*   pos  = (const int*)  d_in[1];
    const int*   neg  = (const int*)  d_in[2];
    const int*   row  = (const int*)  d_in[3];
    const int*   col  = (const int*)  d_in[4];
    const float* vals = (const float*)d_in[5];
    const float* emb  = (const float*)d_in[6];
    const float* W1   = (const float*)d_in[7];
    const float* b1   = (const float*)d_in[8];
    const float* W2   = (const float*)d_in[9];
    const float* b2   = (const float*)d_in[10];
    float* out = (float*)d_out;

    static bool attr_set = false;
    if (!attr_set) {
        cudaFuncSetAttribute(dense_kernel,
                             cudaFuncAttributeMaxDynamicSharedMemorySize, DENSE_SMEM);
        attr_set = true;
    }

    const int EDGE_BLOCKS  = (NNZ + 255) / 256;                 // 4883
    const int ROW16_BLOCKS = (N_NODES * 16 + 255) / 256;        // 7813
    const int DENSE_BLOCKS = (N_NODES + M_TILE - 1) / M_TILE;   // 977

    hist_kernel<<<EDGE_BLOCKS, 256>>>(row);
    scan_lookback_kernel<<<SCAN_BLOCKS, 256>>>();
    scatter_kernel<<<EDGE_BLOCKS, 256>>>(row, col, vals);

    for (int l = 0; l < N_LAYERS; ++l) {
        spmm_csr_kernel<<<ROW16_BLOCKS, 256>>>(emb, l);
        dense_kernel<<<DENSE_BLOCKS, 256, DENSE_SMEM>>>(emb, W1, b1, W2, b2, l);
    }
    gather_kernel<<<(3 * BATCH * 64 + 255) / 256, 256>>>(user, pos, neg, emb, out);
}

// round 15
// speedup vs baseline: 1.1391x; 1.1391x over previous
#include <cuda_runtime.h>
#include <cstdint>

#define N_USERS 50000
#define N_ITEMS 75000
#define N_NODES 125000
#define NNZ     1250000
#define EMB     64
#define N_LAYERS 3
#define BATCH   4096
#define SCAN_BLOCKS 489        // ceil(125000/256)

// Scratch (device globals — allocation-free per harness rules)
__device__ __align__(128) float g_fL0 [N_NODES * EMB];                 // 32 MB
__device__ __align__(128) float g_fL1 [N_NODES * EMB];                 // 32 MB
__device__ __align__(128) float g_fL2 [N_NODES * EMB];                 // 32 MB
__device__ __align__(128) float g_agg [N_NODES * EMB];                 // 32 MB
// CSR scratch.  INVARIANT: g_cnt and g_desc are all-zero at kernel_launch
// entry (zero-initialized at load; re-zeroed by gather_kernel every run).
__device__ __align__(128) int      g_cnt   [N_NODES];
__device__ __align__(128) int2     g_rowse [N_NODES];    // (start, end) per row
__device__ __align__(128) int      g_cursor[N_NODES];
__device__ __align__(128) unsigned g_desc  [512];        // lookback descriptors
__device__ __align__(128) int2     g_edge  [NNZ];        // (col, val_bits) packed

#define FLAG_AGG 0x40000000u
#define FLAG_PRE 0x80000000u
#define VAL_MASK 0x3FFFFFFFu

__device__ __forceinline__ float lrelu(float x) {
    return x > 0.0f ? x : 0.2f * x;
}

// Packed fp32x2 FMA (sm_103a FFMA2)
#define FMA2(acc, a, b) \
    asm("fma.rn.f32x2 %0, %1, %2, %0;" : "+l"(acc) : "l"(a), "l"(b))
#define PACK2(d, s) \
    asm("mov.b64 %0, {%1, %1};" : "=l"(d) : "f"(s))

__device__ __forceinline__ float lo2(unsigned long long v) {
    return __uint_as_float((unsigned)v);
}
__device__ __forceinline__ float hi2(unsigned long long v) {
    return __uint_as_float((unsigned)(v >> 32));
}

// Device-side buffer selection (NEVER pass __device__ symbols from host!)
__device__ __forceinline__ const float* feat_in_for(const float* emb, int layer) {
    return (layer == 0) ? emb : (layer == 1 ? g_fL0 : g_fL1);
}
__device__ __forceinline__ float* feat_out_for(int layer) {
    return (layer == 0) ? g_fL0 : (layer == 1 ? g_fL1 : g_fL2);
}
__device__ __forceinline__ const float* feat_layer(int l) {
    return (l == 0) ? g_fL0 : (l == 1 ? g_fL1 : g_fL2);
}

// ---------------------------------------------------------------------------
// histogram rows (g_cnt zero on entry, see invariant)
__global__ __launch_bounds__(256) void hist_kernel(const int* __restrict__ row) {
    int e = blockIdx.x * 256 + threadIdx.x;
    if (e < NNZ) atomicAdd(&g_cnt[row[e]], 1);
}

// ---------------------------------------------------------------------------
// Single-pass exclusive scan of g_cnt with decoupled lookback.
// Emits packed (start, end) per row + cursor.
__global__ __launch_bounds__(256) void scan_lookback_kernel() {
    __shared__ int wt[8];
    __shared__ int s_run;
    const int tid  = threadIdx.x;
    const int lane = tid & 31;
    const int w    = tid >> 5;
    const int b    = blockIdx.x;
    const int i    = b * 256 + tid;

    int x = (i < N_NODES) ? g_cnt[i] : 0;
    int v = x;
    #pragma unroll
    for (int off = 1; off < 32; off <<= 1) {
        int n = __shfl_up_sync(0xffffffffu, v, off);
        if (lane >= off) v += n;
    }
    if (lane == 31) wt[w] = v;
    __syncthreads();
    if (w == 0 && lane < 8) {
        int s = wt[lane];
        #pragma unroll
        for (int off = 1; off < 8; off <<= 1) {
            int n = __shfl_up_sync(0x000000ffu, s, off);
            if (lane >= off) s += n;
        }
        wt[lane] = s;
    }
    __syncthreads();
    const int add  = (w > 0) ? wt[w - 1] : 0;
    const int excl = v - x + add;
    __syncthreads();
    const int agg  = wt[7];

    if (tid == 0) {
        if (b == 0) {
            atomicExch(&g_desc[0], FLAG_PRE | (unsigned)agg);
            s_run = 0;
        } else {
            atomicExch(&g_desc[b], FLAG_AGG | (unsigned)agg);
            int run = 0;
            int p = b - 1;
            while (true) {
                unsigned s;
                do { s = atomicAdd(&g_desc[p], 0u); } while (s == 0u);
                run += (int)(s & VAL_MASK);
                if (s & FLAG_PRE) break;
                --p;
            }
            atomicExch(&g_desc[b], FLAG_PRE | (unsigned)(run + agg));
            s_run = run;
        }
    }
    __syncthreads();
    const int start = s_run + excl;
    if (i < N_NODES) {
        g_rowse [i] = make_int2(start, start + x);
        g_cursor[i] = start;
    }
}

// scatter edges into row-sorted order, packed (col, val) int2
__global__ __launch_bounds__(256) void scatter_kernel(const int*   __restrict__ row,
                                                      const int*   __restrict__ col,
                                                      const float* __restrict__ vals) {
    int e = blockIdx.x * 256 + threadIdx.x;
    if (e >= NNZ) return;
    int pos = atomicAdd(&g_cursor[row[e]], 1);
    g_edge[pos] = make_int2(col[e], __float_as_int(vals[e]));
}

// ---------------------------------------------------------------------------
// Gather-SpMM over CSR: packed int2 edges + packed (start,end) rowptr.
__global__ __launch_bounds__(256) void spmm_csr_kernel(const float* __restrict__ emb,
                                                       int layer) {
    int t   = blockIdx.x * 256 + threadIdx.x;
    int r   = t >> 4;
    int seg = t & 15;
    if (r >= N_NODES) return;
    const float4* feat4 = (const float4*)feat_in_for(emb, layer);
    int2 se = __ldg(g_rowse + r);
    int j  = se.x;
    int s1 = se.y;
    float4 acc = make_float4(0.f, 0.f, 0.f, 0.f);
    for (; j + 3 < s1; j += 4) {
        int2 e0 = __ldg(g_edge + j);
        int2 e1 = __ldg(g_edge + j + 1);
        int2 e2 = __ldg(g_edge + j + 2);
        int2 e3 = __ldg(g_edge + j + 3);
        float4 f0 = __ldg(feat4 + e0.x * 16 + seg);
        float4 f1 = __ldg(feat4 + e1.x * 16 + seg);
        float4 f2 = __ldg(feat4 + e2.x * 16 + seg);
        float4 f3 = __ldg(feat4 + e3.x * 16 + seg);
        float v0 = __int_as_float(e0.y);
        float v1 = __int_as_float(e1.y);
        float v2 = __int_as_float(e2.y);
        float v3 = __int_as_float(e3.y);
        acc.x += v0 * f0.x + v1 * f1.x + v2 * f2.x + v3 * f3.x;
        acc.y += v0 * f0.y + v1 * f1.y + v2 * f2.y + v3 * f3.y;
        acc.z += v0 * f0.z + v1 * f1.z + v2 * f2.z + v3 * f3.z;
        acc.w += v0 * f0.w + v1 * f1.w + v2 * f2.w + v3 * f3.w;
    }
    for (; j < s1; ++j) {
        int2 e0 = __ldg(g_edge + j);
        float4 f0 = __ldg(feat4 + e0.x * 16 + seg);
        float v0 = __int_as_float(e0.y);
        acc.x += v0 * f0.x;
        acc.y += v0 * f0.y;
        acc.z += v0 * f0.z;
        acc.w += v0 * f0.w;
    }
    ((float4*)g_agg)[r * 16 + seg] = acc;
}

// ---------------------------------------------------------------------------
// Dense per-node update (EXACT R4 core: pair-interleaved m-major, grid 977).
// Epilogue stores feat_out only — NO norm computation (moved to gather).
#define M_TILE      128
#define PAIR_STRIDE 130
#define W_STRIDE    68
#define SA_FLOATS   (64 * PAIR_STRIDE)
#define SW_FLOATS   (64 * W_STRIDE)
#define DENSE_SMEM  ((2 * SA_FLOATS + 2 * SW_FLOATS) * 4)   // 101376 B

__global__ __launch_bounds__(256, 2) void dense_kernel(const float* __restrict__ emb,
                                                       const float* __restrict__ W1,
                                                       const float* __restrict__ b1,
                                                       const float* __restrict__ W2,
                                                       const float* __restrict__ b2,
                                                       int layer) {
    extern __shared__ float smem[];
    float* sA  = smem;
    float* sAF = sA  + SA_FLOATS;
    float* sW1 = sAF + SA_FLOATS;
    float* sW2 = sW1 + SW_FLOATS;

    const float* feat_in  = feat_in_for(emb, layer);
    float*       feat_out = feat_out_for(layer);

    const int t    = threadIdx.x;
    const int tx   = t & 15;
    const int ty   = t >> 4;
    const int j0   = tx * 4;
    const int base = blockIdx.x * M_TILE;

    const float* W1l = W1 + layer * 4096;
    const float* W2l = W2 + layer * 4096;
    #pragma unroll
    for (int i = t; i < 4096; i += 256) {
        int j = i >> 6, k = i & 63;
        sW1[k * W_STRIDE + j] = W1l[i];
        sW2[k * W_STRIDE + j] = W2l[i];
    }

    #pragma unroll
    for (int idx = t; idx < M_TILE * 16; idx += 256) {
        int mm   = idx >> 4;
        int seg  = idx & 15;
        int node = base + mm;
        float4 a4 = make_float4(0.f, 0.f, 0.f, 0.f);
        float4 f4 = make_float4(0.f, 0.f, 0.f, 0.f);
        if (node < N_NODES) {
            a4 = ((const float4*)g_agg  )[node * 16 + seg];
            f4 = ((const float4*)feat_in)[node * 16 + seg];
        }
        int pbase = (mm >> 1) * PAIR_STRIDE + (mm & 1);
        #pragma unroll
        for (int i = 0; i < 4; ++i) {
            float av = (&a4.x)[i];
            float fv = (&f4.x)[i];
            int off = pbase + (seg * 4 + i) * 2;
            sA [off] = av;
            sAF[off] = av * fv;
        }
    }
    __syncthreads();

    unsigned long long acc1[16], acc2[16];
    #pragma unroll
    for (int i = 0; i < 16; ++i) { acc1[i] = 0ull; acc2[i] = 0ull; }

    const int p0 = ty * 4;

    #pragma unroll 8
    for (int k = 0; k < 64; ++k) {
        unsigned long long A2[4], AF2[4];
        #pragma unroll
        for (int mp = 0; mp < 4; ++mp) {
            A2 [mp] = *(const unsigned long long*)(sA  + (p0 + mp) * PAIR_STRIDE + 2 * k);
            AF2[mp] = *(const unsigned long long*)(sAF + (p0 + mp) * PAIR_STRIDE + 2 * k);
        }
        float4 w1 = *(const float4*)(sW1 + k * W_STRIDE + j0);
        float4 w2 = *(const float4*)(sW2 + k * W_STRIDE + j0);
        #pragma unroll
        for (int j = 0; j < 4; ++j) {
            unsigned long long wd1, wd2;
            PACK2(wd1, (&w1.x)[j]);
            PACK2(wd2, (&w2.x)[j]);
            #pragma unroll
            for (int mp = 0; mp < 4; ++mp) {
                FMA2(acc1[j * 4 + mp], A2[mp],  wd1);
                FMA2(acc2[j * 4 + mp], AF2[mp], wd2);
            }
        }
    }

    float bb1[4], bb2[4];
    #pragma unroll
    for (int j = 0; j < 4; ++j) {
        bb1[j] = __ldg(b1 + layer * 64 + j0 + j);
        bb2[j] = __ldg(b2 + layer * 64 + j0 + j);
    }

    #pragma unroll
    for (int mp = 0; mp < 4; ++mp) {
        #pragma unroll
        for (int h = 0; h < 2; ++h) {
            int node = base + ty * 8 + mp * 2 + h;
            if (node < N_NODES) {
                float o[4];
                #pragma unroll
                for (int j = 0; j < 4; ++j) {
                    unsigned long long v1 = acc1[j * 4 + mp];
                    unsigned long long v2 = acc2[j * 4 + mp];
                    float a1 = (h ? hi2(v1) : lo2(v1)) + bb1[j];
                    float a2 = (h ? hi2(v2) : lo2(v2)) + bb2[j];
                    o[j] = lrelu(a1) + lrelu(a2);
                }
                float4 ov = make_float4(o[0], o[1], o[2], o[3]);
                ((float4*)feat_out)[node * 16 + tx] = ov;
            }
        }
    }
}

// ---------------------------------------------------------------------------
// Final gather with ON-THE-FLY normalization: out row = concat(emb, n0,n1,n2)
// where nL = feat_L[node] / max(||feat_L[node]||, eps).  The 16 threads of a
// row-part are consecutive lanes; a 4-step shfl_xor (8,4,2,1) reduces within
// the 16-lane group (lane bits 0..3 only).  Executed unconditionally for all
// lanes so the full-mask shfl is uniform.
// Also re-zeroes g_cnt and g_desc to maintain the entry invariant.
__global__ __launch_bounds__(256) void gather_kernel(const int* __restrict__ user,
                                                     const int* __restrict__ pos,
                                                     const int* __restrict__ neg,
                                                     const float* __restrict__ emb,
                                                     float* __restrict__ out) {
    int o4 = blockIdx.x * 256 + threadIdx.x;
    if (o4 < N_NODES) g_cnt[o4] = 0;               // restore invariant
    if (o4 < 512)     g_desc[o4] = 0u;             // restore invariant
    if (o4 >= 3 * BATCH * 64) return;              // grid is exact: no partial warps
    int c4 = o4 & 63;
    int rr = o4 >> 6;
    int tsel = rr / BATCH;
    int r    = rr - tsel * BATCH;
    int node = (tsel == 0) ? user[r]
             : (tsel == 1) ? (N_USERS + pos[r])
                           : (N_USERS + neg[r]);
    int part = c4 >> 4;
    int cc   = c4 & 15;
    float4 v;
    if (part == 0)
        v = ((const float4*)emb)[node * 16 + cc];
    else
        v = ((const float4*)feat_layer(part - 1))[node * 16 + cc];

    // 16-lane group reduction of sum-of-squares (uniform across warp)
    float ss = v.x * v.x + v.y * v.y + v.z * v.z + v.w * v.w;
    #pragma unroll
    for (int off = 8; off; off >>= 1)
        ss += __shfl_xor_sync(0xffffffffu, ss, off);

    if (part != 0) {
        float inv = __fdividef(1.0f, fmaxf(sqrtf(ss), 1e-12f));
        v.x *= inv; v.y *= inv; v.z *= inv; v.w *= inv;
    }
    ((float4*)out)[o4] = v;
}

// ---------------------------------------------------------------------------
extern "C" void kernel_launch(void* const* d_in, const int* in_sizes, int n_in,
                              void* d_out, int out_size) {
    const int*   user = (const int*)  d_in[0];
    const int*   pos  = (const int*)  d_in[1];
    const int*   neg  = (const int*)  d_in[2];
    const int*   row  = (const int*)  d_in[3];
    const int*   col  = (const int*)  d_in[4];
    const float* vals = (const float*)d_in[5];
    const float* emb  = (const float*)d_in[6];
    const float* W1   = (const float*)d_in[7];
    const float* b1   = (const float*)d_in[8];
    const float* W2   = (const float*)d_in[9];
    const float* b2   = (const float*)d_in[10];
    float* out = (float*)d_out;

    static bool attr_set = false;
    if (!attr_set) {
        cudaFuncSetAttribute(dense_kernel,
                             cudaFuncAttributeMaxDynamicSharedMemorySize, DENSE_SMEM);
        attr_set = true;
    }

    const int EDGE_BLOCKS  = (NNZ + 255) / 256;                 // 4883
    const int ROW16_BLOCKS = (N_NODES * 16 + 255) / 256;        // 7813
    const int DENSE_BLOCKS = (N_NODES + M_TILE - 1) / M_TILE;   // 977

    hist_kernel<<<EDGE_BLOCKS, 256>>>(row);
    scan_lookback_kernel<<<SCAN_BLOCKS, 256>>>();
    scatter_kernel<<<EDGE_BLOCKS, 256>>>(row, col, vals);

    for (int l = 0; l < N_LAYERS; ++l) {
        spmm_csr_kernel<<<ROW16_BLOCKS, 256>>>(emb, l);
        dense_kernel<<<DENSE_BLOCKS, 256, DENSE_SMEM>>>(emb, W1, b1, W2, b2, l);
    }
    gather_kernel<<<(3 * BATCH * 64 + 255) / 256, 256>>>(user, pos, neg, emb, out);
}